// round 1
// baseline (speedup 1.0000x reference)
#include <cuda_runtime.h>
#include <math.h>

// Problem constants
#define N_EQ   131072
#define N_INIT 4096
#define N_BND  4096
#define N_TOT  (N_EQ + N_INIT + N_BND)     // 139264
#define NTILES (N_TOT / 4)                 // 34816, exact

__device__ __forceinline__ float dnu() { return 0.0031830988618379067154f; } // 0.01/pi

// Shared memory layout (bytes):
//   st   : 2 ping-pong buffers [2][4 points][128 neurons] float4   = 16384
//   sW   : W1,W2,W3 each 128x128 floats                            = 196608
//   sW0  : 2x128 floats                                            = 1024
//   sB   : b0,b1,b2,b3 each 128 floats                             = 2048
//   sW4  : 128 floats                                              = 512
// total = 216576 bytes
#define SMEM_BYTES 216576

extern __shared__ char smem_raw[];

__global__ __launch_bounds__(512, 1)
void pinn_kernel(const float* __restrict__ tx_eq,
                 const float* __restrict__ tx_init,
                 const float* __restrict__ tx_bnd,
                 const float* __restrict__ W0, const float* __restrict__ b0,
                 const float* __restrict__ W1, const float* __restrict__ b1,
                 const float* __restrict__ W2, const float* __restrict__ b2,
                 const float* __restrict__ W3, const float* __restrict__ b3,
                 const float* __restrict__ W4, const float* __restrict__ b4,
                 float* __restrict__ out)
{
    float4* st  = (float4*)smem_raw;                       // [2][4][128]
    float*  sW  = (float*)(smem_raw + 16384);              // 3 * 16384 floats
    float*  sW0 = sW + 3 * 16384;                          // 256
    float*  sB  = sW0 + 256;                               // 4 * 128 (b0..b3)
    float*  sW4 = sB + 512;                                // 128

    const int j   = threadIdx.x;       // neuron index 0..127
    const int y   = threadIdx.y;       // point-in-tile 0..3
    const int tid = y * 128 + j;

    // Cooperative weight load (once per block; blocks are persistent)
    for (int i = tid; i < 16384; i += 512) {
        sW[i]           = W1[i];
        sW[16384 + i]   = W2[i];
        sW[32768 + i]   = W3[i];
    }
    if (tid < 256) sW0[tid] = W0[tid];
    if (tid < 128) {
        sB[tid]       = b0[tid];
        sB[128 + tid] = b1[tid];
        sB[256 + tid] = b2[tid];
        sB[384 + tid] = b3[tid];
        sW4[tid]      = W4[tid];
    }
    __syncthreads();

    const float bias4 = b4[0];

    for (int tile = blockIdx.x; tile < NTILES; tile += gridDim.x) {
        const int p = tile * 4 + y;

        float2 tx;
        if (p < N_EQ)                 tx = ((const float2*)tx_eq)[p];
        else if (p < N_EQ + N_INIT)   tx = ((const float2*)tx_init)[p - N_EQ];
        else                          tx = ((const float2*)tx_bnd)[p - N_EQ - N_INIT];

        // ---- Layer 0: 2 -> 128, tanh. Seeds: dt=(1,0), dx=(0,1), d2x=0 ----
        {
            const float wt = sW0[j];         // dz/dt
            const float wx = sW0[128 + j];   // dz/dx
            const float z  = fmaf(wt, tx.x, fmaf(wx, tx.y, sB[j]));
            const float a  = tanhf(z);
            const float ap = 1.0f - a * a;               // a'
            const float at = ap * wt;
            const float ax = ap * wx;
            const float axx = -2.0f * a * ap * wx * wx;  // a''*zx^2 (zxx=0)
            st[(0 * 4 + y) * 128 + j] = make_float4(a, at, ax, axx);
        }
        __syncthreads();

        // ---- Layers 1..3: 128 -> 128, tanh, forward-mode propagation ----
        int buf = 0;
        #pragma unroll
        for (int l = 0; l < 3; l++) {
            const float*  W   = sW + l * 16384;            // [k][j]
            const float4* sin = st + (buf * 4 + y) * 128;

            float a0 = sB[(l + 1) * 128 + j];
            float a1 = 0.0f, a2 = 0.0f, a3 = 0.0f;
            #pragma unroll 8
            for (int k = 0; k < 128; k++) {
                const float  w = W[k * 128 + j];   // conflict-free across lanes
                const float4 s = sin[k];           // broadcast LDS.128
                a0 = fmaf(w, s.x, a0);
                a1 = fmaf(w, s.y, a1);
                a2 = fmaf(w, s.z, a2);
                a3 = fmaf(w, s.w, a3);
            }
            const float a  = tanhf(a0);
            const float ap = 1.0f - a * a;
            const float at = ap * a1;
            const float ax = ap * a2;
            // axx = ap*zxx + a''*zx^2 = ap*(zxx - 2*a*zx^2)
            const float axx = ap * fmaf(-2.0f * a * a2, a2, a3);
            st[((buf ^ 1) * 4 + y) * 128 + j] = make_float4(a, at, ax, axx);
            buf ^= 1;
            __syncthreads();
        }

        // ---- Layer 4: 128 -> 1 linear, reduce within one warp per point ----
        if (j < 32) {
            const float4* sin = st + (buf * 4 + y) * 128;
            float r0 = 0.0f, r1 = 0.0f, r2 = 0.0f, r3 = 0.0f;
            #pragma unroll
            for (int m = 0; m < 4; m++) {
                const int    k = j + 32 * m;
                const float  w = sW4[k];
                const float4 s = sin[k];
                r0 = fmaf(w, s.x, r0);
                r1 = fmaf(w, s.y, r1);
                r2 = fmaf(w, s.z, r2);
                r3 = fmaf(w, s.w, r3);
            }
            #pragma unroll
            for (int off = 16; off > 0; off >>= 1) {
                r0 += __shfl_down_sync(0xffffffffu, r0, off);
                r1 += __shfl_down_sync(0xffffffffu, r1, off);
                r2 += __shfl_down_sync(0xffffffffu, r2, off);
                r3 += __shfl_down_sync(0xffffffffu, r3, off);
            }
            if (j == 0) {
                const float u   = r0 + bias4;
                const float u_t = r1;
                const float u_x = r2;
                const float uxx = r3;
                float val;
                if (p < N_EQ) {
                    // burgers residual: u_t + u*u_x - NU*u_xx
                    val = fmaf(u, u_x, u_t) - dnu() * uxx;
                } else {
                    val = u;   // init/boundary: just u
                }
                out[p] = val;
            }
        }
        __syncthreads();
    }
}

extern "C" void kernel_launch(void* const* d_in, const int* in_sizes, int n_in,
                              void* d_out, int out_size)
{
    const float* tx_eq   = (const float*)d_in[0];
    const float* tx_init = (const float*)d_in[1];
    const float* tx_bnd  = (const float*)d_in[2];
    const float* W0 = (const float*)d_in[3];
    const float* b0 = (const float*)d_in[4];
    const float* W1 = (const float*)d_in[5];
    const float* b1 = (const float*)d_in[6];
    const float* W2 = (const float*)d_in[7];
    const float* b2 = (const float*)d_in[8];
    const float* W3 = (const float*)d_in[9];
    const float* b3 = (const float*)d_in[10];
    const float* W4 = (const float*)d_in[11];
    const float* b4 = (const float*)d_in[12];
    float* out = (float*)d_out;

    cudaFuncSetAttribute(pinn_kernel,
                         cudaFuncAttributeMaxDynamicSharedMemorySize,
                         SMEM_BYTES);

    int sms = 148;
    cudaDeviceGetAttribute(&sms, cudaDevAttrMultiProcessorCount, 0);

    dim3 block(128, 4);
    pinn_kernel<<<sms, block, SMEM_BYTES>>>(
        tx_eq, tx_init, tx_bnd,
        W0, b0, W1, b1, W2, b2, W3, b3, W4, b4,
        out);
}

// round 2
// speedup vs baseline: 1.4616x; 1.4616x over previous
#include <cuda_runtime.h>
#include <stdint.h>

#define N_EQ    131072
#define N_TOT   139264
#define NTILES  8704            // 139264 / 16
#define TILE_EQ 8192            // tiles covering tx_equation
#define TILE_IB 8448            // tiles covering tx_init end
#define NU      0.0031830988618379067154f

typedef unsigned long long u64;

__device__ __forceinline__ u64 pk2(float lo, float hi) {
    u64 r; asm("mov.b64 %0, {%1, %2};" : "=l"(r) : "f"(lo), "f"(hi)); return r;
}
__device__ __forceinline__ void upk2(u64 v, float& lo, float& hi) {
    asm("mov.b64 {%0, %1}, %2;" : "=f"(lo), "=f"(hi) : "l"(v));
}
__device__ __forceinline__ void fma2(u64& d, u64 a, u64 b) {
    asm("fma.rn.f32x2 %0, %1, %2, %0;" : "+l"(d) : "l"(a), "l"(b));
}
__device__ __forceinline__ u64 add2(u64 a, u64 b) {
    u64 r; asm("add.rn.f32x2 %0, %1, %2;" : "=l"(r) : "l"(a), "l"(b)); return r;
}
__device__ __forceinline__ float tanhf_fast(float z) {
    float e = __expf(2.0f * z);
    return __fdividef(e - 1.0f, e + 1.0f);
}

// Shared memory layout (bytes):
//   sW  : W1,W2,W3 each 128x128 floats              = 196608  @ 0
//   st  : float4 [128 rows][17 cols] (16 data+1 pad) =  34816  @ 196608
//   sW4 : 128 floats                                 =    512  @ 231424
#define SMEM_BYTES 231936

extern __shared__ char smem_raw[];

__global__ __launch_bounds__(256, 1)
void pinn_kernel(const float* __restrict__ tx_eq,
                 const float* __restrict__ tx_init,
                 const float* __restrict__ tx_bnd,
                 const float* __restrict__ W0, const float* __restrict__ b0,
                 const float* __restrict__ W1, const float* __restrict__ b1,
                 const float* __restrict__ W2, const float* __restrict__ b2,
                 const float* __restrict__ W3, const float* __restrict__ b3,
                 const float* __restrict__ W4, const float* __restrict__ b4,
                 float* __restrict__ out)
{
    float*  sW  = (float*)smem_raw;                    // 3*16384 floats
    float4* st  = (float4*)(smem_raw + 196608);        // [128][17]
    float*  sW4 = (float*)(smem_raw + 231424);         // 128

    const int tid = threadIdx.x;      // 0..255
    const int j   = tid & 127;        // neuron index
    const int y   = tid >> 7;         // point-group half

    // Cooperative load of the three 128x128 weight matrices (once; persistent)
    {
        float4*       d  = (float4*)sW;
        const float4* s1 = (const float4*)W1;
        const float4* s2 = (const float4*)W2;
        const float4* s3 = (const float4*)W3;
        for (int i = tid; i < 4096; i += 256) {
            d[i]        = s1[i];
            d[4096 + i] = s2[i];
            d[8192 + i] = s3[i];
        }
        if (tid < 128) sW4[tid] = W4[tid];
    }
    // Per-thread small params in registers (saves smem to fit 227KB budget)
    const float w0t = __ldg(W0 + j);
    const float w0x = __ldg(W0 + 128 + j);
    const float b0j = __ldg(b0 + j);
    const float bl0 = __ldg(b1 + j);
    const float bl1 = __ldg(b2 + j);
    const float bl2 = __ldg(b3 + j);
    const float b4s = __ldg(b4);
    __syncthreads();

    const int warp = tid >> 5;
    const int lane = tid & 31;

    for (int tile = blockIdx.x; tile < NTILES; tile += gridDim.x) {
        // Each tile = 16 consecutive points, entirely inside one input array.
        const float4* src4;
        if (tile < TILE_EQ)      src4 = (const float4*)tx_eq  + tile * 8;
        else if (tile < TILE_IB) src4 = (const float4*)tx_init + (tile - TILE_EQ) * 8;
        else                     src4 = (const float4*)tx_bnd  + (tile - TILE_IB) * 8;

        // ---- Layer 0: 2 -> 128, tanh; seeds dt=(1,0), dx=(0,1), d2x=0 ----
        #pragma unroll
        for (int qq = 0; qq < 4; qq++) {
            const int Q = 4 * y + qq;              // point-pair 0..7
            float4 tx2 = __ldg(src4 + Q);          // (t0,x0,t1,x1)
            float z0 = fmaf(w0t, tx2.x, fmaf(w0x, tx2.y, b0j));
            float z1 = fmaf(w0t, tx2.z, fmaf(w0x, tx2.w, b0j));
            float a0 = tanhf_fast(z0), a1 = tanhf_fast(z1);
            float ap0 = 1.0f - a0 * a0, ap1 = 1.0f - a1 * a1;
            float ax0 = ap0 * w0x, ax1 = ap1 * w0x;
            st[j * 17 + Q * 2]     = make_float4(a0, a1, ap0 * w0t, ap1 * w0t);
            st[j * 17 + Q * 2 + 1] = make_float4(ax0, ax1,
                                                 -2.0f * a0 * ax0 * w0x,
                                                 -2.0f * a1 * ax1 * w0x);
        }
        __syncthreads();

        // ---- Layers 1..3: 128 -> 128, tanh, forward-mode AD ----
        #pragma unroll
        for (int l = 0; l < 3; l++) {
            const float* Wl = sW + l * 16384 + j;
            const float  bj = (l == 0) ? bl0 : ((l == 1) ? bl1 : bl2);

            u64 aA[4], aT[4], aX[4], aXX[4];
            #pragma unroll
            for (int q = 0; q < 4; q++) {
                aA[q] = pk2(bj, bj); aT[q] = 0ull; aX[q] = 0ull; aXX[q] = 0ull;
            }

            #pragma unroll 8
            for (int k = 0; k < 128; k++) {
                const float w  = Wl[k * 128];      // conflict-free LDS.32
                const u64   w2 = pk2(w, w);
                const float4* row = st + k * 17;
                #pragma unroll
                for (int qq = 0; qq < 4; qq++) {
                    const int Q = 4 * y + qq;
                    ulonglong2 u0 = *(const ulonglong2*)(row + 2 * Q);     // (a0,a1)(t0,t1)
                    ulonglong2 u1 = *(const ulonglong2*)(row + 2 * Q + 1); // (x0,x1)(xx0,xx1)
                    fma2(aA[qq],  w2, u0.x);
                    fma2(aT[qq],  w2, u0.y);
                    fma2(aX[qq],  w2, u1.x);
                    fma2(aXX[qq], w2, u1.y);
                }
            }
            __syncthreads();   // all reads done before rewriting the buffer

            #pragma unroll
            for (int qq = 0; qq < 4; qq++) {
                const int Q = 4 * y + qq;
                float z0, z1, zt0, zt1, zx0, zx1, zxx0, zxx1;
                upk2(aA[qq],  z0,  z1);
                upk2(aT[qq],  zt0, zt1);
                upk2(aX[qq],  zx0, zx1);
                upk2(aXX[qq], zxx0, zxx1);
                float a0 = tanhf_fast(z0), a1 = tanhf_fast(z1);
                float ap0 = 1.0f - a0 * a0, ap1 = 1.0f - a1 * a1;
                float ax0 = ap0 * zx0, ax1 = ap1 * zx1;
                float axx0 = fmaf(-2.0f * a0 * ax0, zx0, ap0 * zxx0);
                float axx1 = fmaf(-2.0f * a1 * ax1, zx1, ap1 * zxx1);
                st[j * 17 + Q * 2]     = make_float4(a0, a1, ap0 * zt0, ap1 * zt1);
                st[j * 17 + Q * 2 + 1] = make_float4(ax0, ax1, axx0, axx1);
            }
            __syncthreads();
        }

        // ---- Layer 4: 128 -> 1 linear; warp w reduces point-pair Q = w ----
        {
            const int Q = warp;    // 0..7
            u64 rA = 0ull, rT = 0ull, rX = 0ull, rXX = 0ull;
            #pragma unroll
            for (int m = 0; m < 4; m++) {
                const int k  = m * 32 + lane;
                const float w = sW4[k];
                const u64 w2 = pk2(w, w);
                ulonglong2 u0 = *(const ulonglong2*)(st + k * 17 + 2 * Q);
                ulonglong2 u1 = *(const ulonglong2*)(st + k * 17 + 2 * Q + 1);
                fma2(rA,  w2, u0.x);
                fma2(rT,  w2, u0.y);
                fma2(rX,  w2, u1.x);
                fma2(rXX, w2, u1.y);
            }
            #pragma unroll
            for (int off = 16; off > 0; off >>= 1) {
                rA  = add2(rA,  __shfl_down_sync(0xffffffffu, rA,  off));
                rT  = add2(rT,  __shfl_down_sync(0xffffffffu, rT,  off));
                rX  = add2(rX,  __shfl_down_sync(0xffffffffu, rX,  off));
                rXX = add2(rXX, __shfl_down_sync(0xffffffffu, rXX, off));
            }
            if (lane == 0) {
                float u0, u1, t0, t1, x0, x1, xx0, xx1;
                upk2(rA, u0, u1); upk2(rT, t0, t1);
                upk2(rX, x0, x1); upk2(rXX, xx0, xx1);
                u0 += b4s; u1 += b4s;
                const int p = tile * 16 + 2 * Q;
                if (tile < TILE_EQ) {
                    out[p]     = fmaf(u0, x0, t0) - NU * xx0;
                    out[p + 1] = fmaf(u1, x1, t1) - NU * xx1;
                } else {
                    out[p]     = u0;
                    out[p + 1] = u1;
                }
            }
        }
        __syncthreads();   // st reads done before next tile's layer-0 stores
    }
}

extern "C" void kernel_launch(void* const* d_in, const int* in_sizes, int n_in,
                              void* d_out, int out_size)
{
    const float* tx_eq   = (const float*)d_in[0];
    const float* tx_init = (const float*)d_in[1];
    const float* tx_bnd  = (const float*)d_in[2];
    const float* W0 = (const float*)d_in[3];
    const float* b0 = (const float*)d_in[4];
    const float* W1 = (const float*)d_in[5];
    const float* b1 = (const float*)d_in[6];
    const float* W2 = (const float*)d_in[7];
    const float* b2 = (const float*)d_in[8];
    const float* W3 = (const float*)d_in[9];
    const float* b3 = (const float*)d_in[10];
    const float* W4 = (const float*)d_in[11];
    const float* b4 = (const float*)d_in[12];
    float* out = (float*)d_out;

    cudaFuncSetAttribute(pinn_kernel,
                         cudaFuncAttributeMaxDynamicSharedMemorySize,
                         SMEM_BYTES);

    int sms = 148;
    cudaDeviceGetAttribute(&sms, cudaDevAttrMultiProcessorCount, 0);
    if (sms > NTILES) sms = NTILES;

    pinn_kernel<<<sms, 256, SMEM_BYTES>>>(
        tx_eq, tx_init, tx_bnd,
        W0, b0, W1, b1, W2, b2, W3, b3, W4, b4,
        out);
}

// round 3
// speedup vs baseline: 2.1040x; 1.4396x over previous
#include <cuda_runtime.h>

#define N_EQ    131072
#define NTILES  8704            // 139264 / 16 points per tile
#define TILE_EQ 8192
#define TILE_IB 8448
#define NU      0.0031830988618379067154f

typedef unsigned long long u64;

__device__ __forceinline__ u64 pk2(float lo, float hi) {
    u64 r; asm("mov.b64 %0, {%1, %2};" : "=l"(r) : "f"(lo), "f"(hi)); return r;
}
__device__ __forceinline__ void upk2(u64 v, float& lo, float& hi) {
    asm("mov.b64 {%0, %1}, %2;" : "=f"(lo), "=f"(hi) : "l"(v));
}
__device__ __forceinline__ void fma2(u64& d, u64 a, u64 b) {
    asm("fma.rn.f32x2 %0, %1, %2, %0;" : "+l"(d) : "l"(a), "l"(b));
}
__device__ __forceinline__ u64 add2(u64 a, u64 b) {
    u64 r; asm("add.rn.f32x2 %0, %1, %2;" : "=l"(r) : "l"(a), "l"(b)); return r;
}
__device__ __forceinline__ float hadd2(u64 v) {
    float lo, hi; upk2(v, lo, hi); return lo + hi;
}
__device__ __forceinline__ float tanhf_fast(float z) {
    float e = __expf(2.0f * z);
    return __fdividef(e - 1.0f, e + 1.0f);
}

// Shared memory (bytes):
//   sWk : 3 layers x 64 kp x 128 j  u64      = 196608  @ 0
//   st  : 16 pt x 64 kp x 4 u64 (32B/pt/kp)  =  32768  @ 196608
//   sW4 : 64 u64                              =    512  @ 229376
//   sB  : b1,b2,b3 (3 x 128 floats)           =   1536  @ 229888
// total = 231424  (<= 232448 limit)
#define SMEM_BYTES 231424

extern __shared__ char smem_raw[];

__global__ __launch_bounds__(256, 1)
void pinn_kernel(const float* __restrict__ tx_eq,
                 const float* __restrict__ tx_init,
                 const float* __restrict__ tx_bnd,
                 const float* __restrict__ W0, const float* __restrict__ b0,
                 const float* __restrict__ W1, const float* __restrict__ b1,
                 const float* __restrict__ W2, const float* __restrict__ b2,
                 const float* __restrict__ W3, const float* __restrict__ b3,
                 const float* __restrict__ W4, const float* __restrict__ b4,
                 float* __restrict__ out)
{
    u64*   sWk = (u64*)smem_raw;                       // [l][kp][j]
    u64*   stU = (u64*)(smem_raw + 196608);            // [pt][kp][4]
    u64*   sW4 = (u64*)(smem_raw + 229376);            // [kp]
    float* sB  = (float*)(smem_raw + 229888);          // [l][j]

    const int tid  = threadIdx.x;
    const int lane = tid & 31;
    const int q    = tid >> 5;          // warp 0..7 -> point pair

    // ---- Build k-pair-interleaved weights in smem (once; persistent) ----
    {
        const float* Wsrc[3] = { W1, W2, W3 };
        #pragma unroll
        for (int l = 0; l < 3; l++) {
            const float* W = Wsrc[l];
            for (int i = tid; i < 8192; i += 256) {
                const int kp = i >> 7, j = i & 127;
                sWk[l * 8192 + i] = pk2(W[(2*kp) * 128 + j], W[(2*kp+1) * 128 + j]);
            }
        }
        if (tid < 64)  sW4[tid] = pk2(W4[2*tid], W4[2*tid+1]);
        if (tid < 128) { sB[tid] = b1[tid]; sB[128+tid] = b2[tid]; sB[256+tid] = b3[tid]; }
    }

    // Layer-0 params for this thread's 4 neurons: j = {2l, 2l+1, 2l+64, 2l+65}
    int jmap[4];
    jmap[0] = 2*lane; jmap[1] = 2*lane + 1; jmap[2] = 2*lane + 64; jmap[3] = 2*lane + 65;
    float w0t[4], w0x[4], b0r[4];
    #pragma unroll
    for (int n = 0; n < 4; n++) {
        w0t[n] = __ldg(W0 + jmap[n]);
        w0x[n] = __ldg(W0 + 128 + jmap[n]);
        b0r[n] = __ldg(b0 + jmap[n]);
    }
    const float b4s = __ldg(b4);
    __syncthreads();

    for (int tile = blockIdx.x; tile < NTILES; tile += gridDim.x) {
        const float2* src;
        if (tile < TILE_EQ)      src = (const float2*)tx_eq  + tile * 16;
        else if (tile < TILE_IB) src = (const float2*)tx_init + (tile - TILE_EQ) * 16;
        else                     src = (const float2*)tx_bnd  + (tile - TILE_IB) * 16;

        const int p0 = 2 * q, p1 = 2 * q + 1;   // this warp's tile-local points

        // ---- Layer 0: 2 -> 128, tanh; seeds zt=w0t, zx=w0x, zxx=0 ----
        {
            const float2 tA = __ldg(src + p0);
            const float2 tB = __ldg(src + p1);
            float a[2][4], at[2][4], ax[2][4], axx[2][4];
            #pragma unroll
            for (int n = 0; n < 4; n++) {
                #pragma unroll
                for (int pt = 0; pt < 2; pt++) {
                    const float2 t = pt ? tB : tA;
                    const float z  = fmaf(w0t[n], t.x, fmaf(w0x[n], t.y, b0r[n]));
                    const float av = tanhf_fast(z);
                    const float ap = 1.0f - av * av;
                    a[pt][n]  = av;
                    at[pt][n] = ap * w0t[n];
                    ax[pt][n] = ap * w0x[n];
                    axx[pt][n] = -2.0f * av * ax[pt][n] * w0x[n];
                }
            }
            #pragma unroll
            for (int pt = 0; pt < 2; pt++) {
                const int p = pt ? p1 : p0;
                u64* d0 = stU + p * 256 + lane * 4;          // kp = lane   (n0,n1)
                u64* d1 = stU + p * 256 + (lane + 32) * 4;   // kp = lane+32 (n2,n3)
                ((ulonglong2*)d0)[0] = make_ulonglong2(pk2(a[pt][0],  a[pt][1]),  pk2(at[pt][0],  at[pt][1]));
                ((ulonglong2*)d0)[1] = make_ulonglong2(pk2(ax[pt][0], ax[pt][1]), pk2(axx[pt][0], axx[pt][1]));
                ((ulonglong2*)d1)[0] = make_ulonglong2(pk2(a[pt][2],  a[pt][3]),  pk2(at[pt][2],  at[pt][3]));
                ((ulonglong2*)d1)[1] = make_ulonglong2(pk2(ax[pt][2], ax[pt][3]), pk2(axx[pt][2], axx[pt][3]));
            }
        }
        __syncthreads();

        // ---- Layers 1..3: 128 -> 128, k-pair packed forward-mode AD ----
        #pragma unroll
        for (int l = 0; l < 3; l++) {
            const u64* Wb  = sWk + l * 8192 + 2 * lane;
            const u64* sp0 = stU + p0 * 256;
            const u64* sp1 = stU + p1 * 256;

            u64 acc[2][4][4];   // [pt][state][neuron]
            #pragma unroll
            for (int pt = 0; pt < 2; pt++)
                #pragma unroll
                for (int s = 0; s < 4; s++)
                    #pragma unroll
                    for (int n = 0; n < 4; n++) acc[pt][s][n] = 0ull;

            #pragma unroll 8
            for (int kp = 0; kp < 64; kp++) {
                const ulonglong2 wA = *(const ulonglong2*)(Wb + kp * 128);        // n0,n1
                const ulonglong2 wB = *(const ulonglong2*)(Wb + kp * 128 + 64);   // n2,n3
                const ulonglong2 s0a = *(const ulonglong2*)(sp0 + kp * 4);        // (a,t)
                const ulonglong2 s0b = *(const ulonglong2*)(sp0 + kp * 4 + 2);    // (x,xx)
                const ulonglong2 s1a = *(const ulonglong2*)(sp1 + kp * 4);
                const ulonglong2 s1b = *(const ulonglong2*)(sp1 + kp * 4 + 2);

                fma2(acc[0][0][0], wA.x, s0a.x); fma2(acc[0][0][1], wA.y, s0a.x);
                fma2(acc[0][0][2], wB.x, s0a.x); fma2(acc[0][0][3], wB.y, s0a.x);
                fma2(acc[0][1][0], wA.x, s0a.y); fma2(acc[0][1][1], wA.y, s0a.y);
                fma2(acc[0][1][2], wB.x, s0a.y); fma2(acc[0][1][3], wB.y, s0a.y);
                fma2(acc[0][2][0], wA.x, s0b.x); fma2(acc[0][2][1], wA.y, s0b.x);
                fma2(acc[0][2][2], wB.x, s0b.x); fma2(acc[0][2][3], wB.y, s0b.x);
                fma2(acc[0][3][0], wA.x, s0b.y); fma2(acc[0][3][1], wA.y, s0b.y);
                fma2(acc[0][3][2], wB.x, s0b.y); fma2(acc[0][3][3], wB.y, s0b.y);

                fma2(acc[1][0][0], wA.x, s1a.x); fma2(acc[1][0][1], wA.y, s1a.x);
                fma2(acc[1][0][2], wB.x, s1a.x); fma2(acc[1][0][3], wB.y, s1a.x);
                fma2(acc[1][1][0], wA.x, s1a.y); fma2(acc[1][1][1], wA.y, s1a.y);
                fma2(acc[1][1][2], wB.x, s1a.y); fma2(acc[1][1][3], wB.y, s1a.y);
                fma2(acc[1][2][0], wA.x, s1b.x); fma2(acc[1][2][1], wA.y, s1b.x);
                fma2(acc[1][2][2], wB.x, s1b.x); fma2(acc[1][2][3], wB.y, s1b.x);
                fma2(acc[1][3][0], wA.x, s1b.y); fma2(acc[1][3][1], wA.y, s1b.y);
                fma2(acc[1][3][2], wB.x, s1b.y); fma2(acc[1][3][3], wB.y, s1b.y);
            }
            __syncthreads();   // all reads of this layer done before rewrites

            float bl[4];
            #pragma unroll
            for (int n = 0; n < 4; n++) bl[n] = sB[l * 128 + jmap[n]];

            #pragma unroll
            for (int pt = 0; pt < 2; pt++) {
                float a[4], at[4], ax[4], axx[4];
                #pragma unroll
                for (int n = 0; n < 4; n++) {
                    const float z   = hadd2(acc[pt][0][n]) + bl[n];
                    const float zt  = hadd2(acc[pt][1][n]);
                    const float zx  = hadd2(acc[pt][2][n]);
                    const float zxx = hadd2(acc[pt][3][n]);
                    const float av  = tanhf_fast(z);
                    const float ap  = 1.0f - av * av;
                    a[n]  = av;
                    at[n] = ap * zt;
                    ax[n] = ap * zx;
                    axx[n] = fmaf(-2.0f * av * ax[n], zx, ap * zxx);
                }
                const int p = pt ? p1 : p0;
                u64* d0 = stU + p * 256 + lane * 4;
                u64* d1 = stU + p * 256 + (lane + 32) * 4;
                ((ulonglong2*)d0)[0] = make_ulonglong2(pk2(a[0],  a[1]),  pk2(at[0],  at[1]));
                ((ulonglong2*)d0)[1] = make_ulonglong2(pk2(ax[0], ax[1]), pk2(axx[0], axx[1]));
                ((ulonglong2*)d1)[0] = make_ulonglong2(pk2(a[2],  a[3]),  pk2(at[2],  at[3]));
                ((ulonglong2*)d1)[1] = make_ulonglong2(pk2(ax[2], ax[3]), pk2(axx[2], axx[3]));
            }
            __syncthreads();
        }

        // ---- Layer 4: 128 -> 1 linear, per-warp reduction over kp ----
        {
            u64 r[2][4] = {{0ull,0ull,0ull,0ull},{0ull,0ull,0ull,0ull}};
            #pragma unroll
            for (int m = 0; m < 2; m++) {
                const int kp = lane + 32 * m;
                const u64 w  = sW4[kp];
                #pragma unroll
                for (int pt = 0; pt < 2; pt++) {
                    const int p = pt ? p1 : p0;
                    const ulonglong2 sa = *(const ulonglong2*)(stU + p * 256 + kp * 4);
                    const ulonglong2 sb = *(const ulonglong2*)(stU + p * 256 + kp * 4 + 2);
                    fma2(r[pt][0], w, sa.x);
                    fma2(r[pt][1], w, sa.y);
                    fma2(r[pt][2], w, sb.x);
                    fma2(r[pt][3], w, sb.y);
                }
            }
            #pragma unroll
            for (int off = 16; off > 0; off >>= 1) {
                #pragma unroll
                for (int pt = 0; pt < 2; pt++)
                    #pragma unroll
                    for (int s = 0; s < 4; s++)
                        r[pt][s] = add2(r[pt][s], __shfl_down_sync(0xffffffffu, r[pt][s], off));
            }
            if (lane == 0) {
                const int pbase = tile * 16 + 2 * q;
                #pragma unroll
                for (int pt = 0; pt < 2; pt++) {
                    const float u   = hadd2(r[pt][0]) + b4s;
                    const float ut  = hadd2(r[pt][1]);
                    const float ux  = hadd2(r[pt][2]);
                    const float uxx = hadd2(r[pt][3]);
                    out[pbase + pt] = (tile < TILE_EQ) ? (fmaf(u, ux, ut) - NU * uxx) : u;
                }
            }
        }
        __syncthreads();   // layer-4 reads done before next tile's layer-0 stores
    }
}

extern "C" void kernel_launch(void* const* d_in, const int* in_sizes, int n_in,
                              void* d_out, int out_size)
{
    const float* tx_eq   = (const float*)d_in[0];
    const float* tx_init = (const float*)d_in[1];
    const float* tx_bnd  = (const float*)d_in[2];
    const float* W0 = (const float*)d_in[3];
    const float* b0 = (const float*)d_in[4];
    const float* W1 = (const float*)d_in[5];
    const float* b1 = (const float*)d_in[6];
    const float* W2 = (const float*)d_in[7];
    const float* b2 = (const float*)d_in[8];
    const float* W3 = (const float*)d_in[9];
    const float* b3 = (const float*)d_in[10];
    const float* W4 = (const float*)d_in[11];
    const float* b4 = (const float*)d_in[12];
    float* out = (float*)d_out;

    cudaFuncSetAttribute(pinn_kernel,
                         cudaFuncAttributeMaxDynamicSharedMemorySize,
                         SMEM_BYTES);

    int sms = 148;
    cudaDeviceGetAttribute(&sms, cudaDevAttrMultiProcessorCount, 0);
    if (sms > NTILES) sms = NTILES;

    pinn_kernel<<<sms, 256, SMEM_BYTES>>>(
        tx_eq, tx_init, tx_bnd,
        W0, b0, W1, b1, W2, b2, W3, b3, W4, b4,
        out);
}